// round 8
// baseline (speedup 1.0000x reference)
#include <cuda_runtime.h>
#include <math.h>

#define B_   32
#define T_   1000
#define F_   80
#define H_   1024
#define HH_  2048
#define NBLK 128
#define EPSV 1e-5f

typedef unsigned long long ull;

// ---------------- scratch (static device globals; no allocation) ----------------
__device__ float  g_w[65536000];               // [32000][2048]
__device__ float  g_hs1[32768000];             // [32000][1024]
__device__ float  g_hTs[2][2][1024 * 16];      // [parity][stream][k][i(16)]
__device__ float  g_colsum[HH_];
__device__ float  g_colsq[HH_];
__device__ float  g_scale[HH_];
__device__ float  g_shift[HH_];
__device__ float2 g_pp[2][2][16 * NBLK];       // [parity][stream][row*NBLK+b]
__device__ unsigned g_cnt[4];                  // [0]=stats s0, [1]=stats s1, [2]=h s0, [3]=h s1

// ---------------- helpers ----------------
union F4U { float4 f; ulonglong2 u; };

__device__ __forceinline__ void fma2(ull& d, ull a, ull b) {
    asm("fma.rn.f32x2 %0, %1, %2, %0;" : "+l"(d) : "l"(a), "l"(b));
}
__device__ __forceinline__ ull pack2(float v) {
    ull r;
    asm("mov.b64 %0, {%1, %1};" : "=l"(r) : "f"(v));
    return r;
}
__device__ __forceinline__ float ulo(ull v) { return __uint_as_float((unsigned)v); }
__device__ __forceinline__ float uhi(ull v) { return __uint_as_float((unsigned)(v >> 32)); }

__device__ __forceinline__ unsigned ld_acq(const unsigned* p) {
    unsigned v;
    asm volatile("ld.acquire.gpu.global.u32 %0, [%1];" : "=r"(v) : "l"(p));
    return v;
}

// ---------------- SGEMM (NT, plain FFMA): C[m][n]=sum_k A[m][k]B[n][k], N=2048 ----
__global__ void __launch_bounds__(256)
sgemm_nt(const float* __restrict__ A, const float* __restrict__ Bm,
         float* __restrict__ C, int K)
{
    __shared__ float As[8][128];
    __shared__ float Bs[8][128];
    const int tid  = threadIdx.x;
    const int m0   = blockIdx.y * 128;
    const int n0   = blockIdx.x * 128;
    const int lrow = tid >> 1;
    const int lk4  = (tid & 1) * 4;
    const int tx   = tid & 15, ty = tid >> 4;
    const float* Ap = A  + (size_t)(m0 + lrow) * K + lk4;
    const float* Bp = Bm + (size_t)(n0 + lrow) * K + lk4;
    float acc[8][8];
    #pragma unroll
    for (int i = 0; i < 8; i++)
        #pragma unroll
        for (int j = 0; j < 8; j++) acc[i][j] = 0.0f;

    for (int k0 = 0; k0 < K; k0 += 8) {
        float4 av = *(const float4*)(Ap + k0);
        float4 bv = *(const float4*)(Bp + k0);
        __syncthreads();
        As[lk4 + 0][lrow] = av.x; As[lk4 + 1][lrow] = av.y;
        As[lk4 + 2][lrow] = av.z; As[lk4 + 3][lrow] = av.w;
        Bs[lk4 + 0][lrow] = bv.x; Bs[lk4 + 1][lrow] = bv.y;
        Bs[lk4 + 2][lrow] = bv.z; Bs[lk4 + 3][lrow] = bv.w;
        __syncthreads();
        #pragma unroll
        for (int kk = 0; kk < 8; kk++) {
            float a[8], bb[8];
            *(float4*)&a[0]  = *(const float4*)&As[kk][ty * 8];
            *(float4*)&a[4]  = *(const float4*)&As[kk][ty * 8 + 4];
            *(float4*)&bb[0] = *(const float4*)&Bs[kk][tx * 8];
            *(float4*)&bb[4] = *(const float4*)&Bs[kk][tx * 8 + 4];
            #pragma unroll
            for (int i = 0; i < 8; i++)
                #pragma unroll
                for (int j = 0; j < 8; j++)
                    acc[i][j] += a[i] * bb[j];
        }
    }
    #pragma unroll
    for (int i = 0; i < 8; i++) {
        float* Cp = C + (size_t)(m0 + ty * 8 + i) * HH_ + n0 + tx * 8;
        *(float4*)Cp       = make_float4(acc[i][0], acc[i][1], acc[i][2], acc[i][3]);
        *(float4*)(Cp + 4) = make_float4(acc[i][4], acc[i][5], acc[i][6], acc[i][7]);
    }
}

// ---------------- BatchNorm column stats over 32000 rows ----------------
__global__ void __launch_bounds__(256)
bn_stats(const float* __restrict__ w)
{
    int col = blockIdx.x * 256 + threadIdx.x;
    size_t r0 = (size_t)blockIdx.y * 1000;
    float s = 0.0f, q = 0.0f;
    const float* p = w + r0 * HH_ + col;
    #pragma unroll 4
    for (int r = 0; r < 1000; r++) {
        float v = p[(size_t)r * HH_];
        s += v; q += v * v;
    }
    atomicAdd(&g_colsum[col], s);
    atomicAdd(&g_colsq[col], q);
}

__global__ void __launch_bounds__(256)
bn_finalize(const float* __restrict__ gamma, const float* __restrict__ beta)
{
    int c = blockIdx.x * 256 + threadIdx.x;
    float mean = g_colsum[c] * (1.0f / 32000.0f);
    float var  = g_colsq[c] * (1.0f / 32000.0f) - mean * mean;
    float sc = gamma[c] * rsqrtf(var + EPSV);
    g_scale[c] = sc;
    g_shift[c] = beta[c] - mean * sc;
}

// ---------------- Persistent LiGRU recurrence (2-stream pipelined) ----------------
// SMEM floats:
//   Us    [1024][16]   @ 0       (16384)
//   red   [16][288]    @ 16384   (4608, stride-18 padded rows)
//   uh0   [256]        @ 20992
//   uh1   [256]        @ 21248
//   scs   [16]         @ 21504
//   shs   [16]         @ 21520   -> 21536 floats = 86144 B
#define REC_SMEM_FLOATS 21536

// per-stream GEMM: rows 16 (i0), cols 16 (jj0), K segment 64
__device__ __forceinline__ void stream_gemm(const float* __restrict__ hseg,
                                            const float* __restrict__ useg,
                                            float* __restrict__ rp,
                                            int i0, int jj0)
{
    ull a00 = 0, a01 = 0, a10 = 0, a11 = 0;
    F4U h0[4], h1[4];
    #pragma unroll
    for (int u = 0; u < 4; u++)
        h0[u].f = __ldcg((const float4*)(hseg + u * 16));
    #pragma unroll
    for (int g = 0; g < 16; ++g) {
        F4U* hc = (g & 1) ? h1 : h0;
        F4U* hn = (g & 1) ? h0 : h1;
        if (g < 15) {
            #pragma unroll
            for (int u = 0; u < 4; u++)
                hn[u].f = __ldcg((const float4*)(hseg + ((g + 1) * 4 + u) * 16));
        }
        #pragma unroll
        for (int u = 0; u < 4; u++) {
            float2 uv = *(const float2*)(useg + (g * 4 + u) * 16);
            ull ux = pack2(uv.x), uy = pack2(uv.y);
            fma2(a00, hc[u].u.x, ux);
            fma2(a10, hc[u].u.y, ux);
            fma2(a01, hc[u].u.x, uy);
            fma2(a11, hc[u].u.y, uy);
        }
    }
    rp[(i0 + 0) * 18 + jj0]     = ulo(a00);
    rp[(i0 + 1) * 18 + jj0]     = uhi(a00);
    rp[(i0 + 2) * 18 + jj0]     = ulo(a10);
    rp[(i0 + 3) * 18 + jj0]     = uhi(a10);
    rp[(i0 + 0) * 18 + jj0 + 1] = ulo(a01);
    rp[(i0 + 1) * 18 + jj0 + 1] = uhi(a01);
    rp[(i0 + 2) * 18 + jj0 + 1] = ulo(a11);
    rp[(i0 + 3) * 18 + jj0 + 1] = uhi(a11);
}

__global__ void __launch_bounds__(512, 1)
rec_kernel(const float* __restrict__ w, const float* __restrict__ U,
           float* __restrict__ hs_out)
{
    extern __shared__ float sm[];
    float* Us  = sm;
    float* red = sm + 16384;
    float* uh0 = sm + 20992;
    float* uh1 = sm + 21248;
    float* scs = sm + 21504;
    float* shs = sm + 21520;

    const int tid = threadIdx.x;
    const int b   = blockIdx.x;
    const int cb  = b * 8;

    for (int idx = tid; idx < 16 * 1024; idx += 512) {
        int jj = idx >> 10, k = idx & 1023;
        int urow = (jj < 8) ? (cb + jj) : (H_ + cb + jj - 8);
        Us[k * 16 + jj] = U[(size_t)urow * H_ + k];
    }
    if (tid < 16) {
        int col = (tid < 8) ? (cb + tid) : (H_ + cb + tid - 8);
        scs[tid] = g_scale[col];
        shs[tid] = g_shift[col];
    }
    __syncthreads();

    const int warp  = tid >> 5, lane = tid & 31;
    const int i0    = (lane & 3) * 4;      // 4 rows within 16
    const int jj0   = (lane >> 2) * 2;     // 2 gate cols within 16
    const int kbase = warp * 64;

    const int ui = tid >> 3;               // update row (tid<128): 0..15
    const int uj = tid & 7;                // update h-col within block

    float hreg0 = 0.0f, hreg1 = 0.0f;

    const float* useg = Us + kbase * 16 + jj0;
    float* rp = red + warp * 288;

    for (int t = 0; t < T_; ++t) {
        const int par = t & 1;

        // prefetch both streams' w rows for this thread's update slot
        float wa0 = 0.f, wz0 = 0.f, wa1 = 0.f, wz1 = 0.f;
        if (tid < 128) {
            size_t r0 = (size_t)(ui * T_ + t) * HH_;
            size_t r1 = (size_t)((16 + ui) * T_ + t) * HH_;
            wa0 = __ldg(w + r0 + cb + uj);
            wz0 = __ldg(w + r0 + H_ + cb + uj);
            wa1 = __ldg(w + r1 + cb + uj);
            wz1 = __ldg(w + r1 + H_ + cb + uj);
        }

        // ---- phase A: stream 0 GEMM ----
        if (tid == 0 && t > 0) {
            const unsigned tgt = (unsigned)t * NBLK;
            while (ld_acq(&g_cnt[2]) < tgt) { }
        }
        __syncthreads();
        stream_gemm(g_hTs[par ^ 1][0] + kbase * 16 + i0, useg, rp, i0, jj0);
        __syncthreads();
        if (tid < 256) {
            float v = 0.0f;
            const int off = (tid >> 4) * 18 + (tid & 15);
            #pragma unroll
            for (int wv = 0; wv < 16; wv++) v += red[wv * 288 + off];
            uh0[tid] = v;
            float S = v, Q = v * v;
            #pragma unroll
            for (int d = 8; d >= 1; d >>= 1) {
                S += __shfl_xor_sync(0xffffffffu, S, d, 16);
                Q += __shfl_xor_sync(0xffffffffu, Q, d, 16);
            }
            if ((tid & 15) == 0)
                g_pp[par][0][(tid >> 4) * NBLK + b] = make_float2(S, Q);
        }
        __syncthreads();
        if (tid == 0) {
            __threadfence();
            atomicAdd(&g_cnt[0], 1u);
        }

        // ---- phase B: stream 1 GEMM (overlaps other blocks' s0 publishes) ----
        if (tid == 0 && t > 0) {
            const unsigned tgt = (unsigned)t * NBLK;
            while (ld_acq(&g_cnt[3]) < tgt) { }
        }
        __syncthreads();
        stream_gemm(g_hTs[par ^ 1][1] + kbase * 16 + i0, useg, rp, i0, jj0);
        __syncthreads();
        if (tid < 256) {
            float v = 0.0f;
            const int off = (tid >> 4) * 18 + (tid & 15);
            #pragma unroll
            for (int wv = 0; wv < 16; wv++) v += red[wv * 288 + off];
            uh1[tid] = v;
            float S = v, Q = v * v;
            #pragma unroll
            for (int d = 8; d >= 1; d >>= 1) {
                S += __shfl_xor_sync(0xffffffffu, S, d, 16);
                Q += __shfl_xor_sync(0xffffffffu, Q, d, 16);
            }
            if ((tid & 15) == 0)
                g_pp[par][1][(tid >> 4) * NBLK + b] = make_float2(S, Q);
        }
        __syncthreads();
        if (tid == 0) {
            __threadfence();
            atomicAdd(&g_cnt[1], 1u);
        }

        // ---- phase C: stream 0 update (stats wait mostly hidden by phase B) ----
        if (tid == 0) {
            const unsigned tgt = (unsigned)(t + 1) * NBLK;
            while (ld_acq(&g_cnt[0]) < tgt) { }
        }
        __syncthreads();
        float hn0 = 0.0f;
        if (tid < 128) {
            const float2* pp = g_pp[par][0] + ui * NBLK + uj * 16;
            float S = 0.f, Q = 0.f;
            #pragma unroll
            for (int q = 0; q < 16; q++) {
                float2 v = __ldcg(pp + q);
                S += v.x; Q += v.y;
            }
            #pragma unroll
            for (int d = 4; d >= 1; d >>= 1) {
                S += __shfl_xor_sync(0xffffffffu, S, d, 8);
                Q += __shfl_xor_sync(0xffffffffu, Q, d, 8);
            }
            float mean = S * (1.0f / 2048.0f);
            float var  = Q * (1.0f / 2048.0f) - mean * mean;
            float rstd = rsqrtf(var + EPSV);
            float an = (uh0[ui * 16 + uj]     - mean) * rstd;
            float zn = (uh0[ui * 16 + 8 + uj] - mean) * rstd;
            float a  = wa0 * scs[uj]     + shs[uj]     + an;
            float zx = wz0 * scs[8 + uj] + shs[8 + uj] + zn;
            float z  = 1.0f / (1.0f + __expf(-zx));
            hn0 = z * hreg0 + (1.0f - z) * fmaxf(a, 0.0f);
            hreg0 = hn0;
            g_hTs[par][0][(cb + uj) * 16 + ui] = hn0;
        }
        __syncthreads();
        if (tid == 0) {
            __threadfence();
            atomicAdd(&g_cnt[2], 1u);
        }
        if (tid < 128)
            hs_out[(size_t)(ui * T_ + t) * H_ + cb + uj] = hn0;

        // ---- phase D: stream 1 update ----
        if (tid == 0) {
            const unsigned tgt = (unsigned)(t + 1) * NBLK;
            while (ld_acq(&g_cnt[1]) < tgt) { }
        }
        __syncthreads();
        float hn1 = 0.0f;
        if (tid < 128) {
            const float2* pp = g_pp[par][1] + ui * NBLK + uj * 16;
            float S = 0.f, Q = 0.f;
            #pragma unroll
            for (int q = 0; q < 16; q++) {
                float2 v = __ldcg(pp + q);
                S += v.x; Q += v.y;
            }
            #pragma unroll
            for (int d = 4; d >= 1; d >>= 1) {
                S += __shfl_xor_sync(0xffffffffu, S, d, 8);
                Q += __shfl_xor_sync(0xffffffffu, Q, d, 8);
            }
            float mean = S * (1.0f / 2048.0f);
            float var  = Q * (1.0f / 2048.0f) - mean * mean;
            float rstd = rsqrtf(var + EPSV);
            float an = (uh1[ui * 16 + uj]     - mean) * rstd;
            float zn = (uh1[ui * 16 + 8 + uj] - mean) * rstd;
            float a  = wa1 * scs[uj]     + shs[uj]     + an;
            float zx = wz1 * scs[8 + uj] + shs[8 + uj] + zn;
            float z  = 1.0f / (1.0f + __expf(-zx));
            hn1 = z * hreg1 + (1.0f - z) * fmaxf(a, 0.0f);
            hreg1 = hn1;
            g_hTs[par][1][(cb + uj) * 16 + ui] = hn1;
        }
        __syncthreads();
        if (tid == 0) {
            __threadfence();
            atomicAdd(&g_cnt[3], 1u);
        }
        if (tid < 128)
            hs_out[(size_t)((16 + ui) * T_ + t) * H_ + cb + uj] = hn1;
    }
}

// ---------------- launch ----------------
extern "C" void kernel_launch(void* const* d_in, const int* in_sizes, int n_in,
                              void* d_out, int out_size)
{
    const float* x  = (const float*)d_in[0];
    const float* W1 = (const float*)d_in[1];
    const float* U1 = (const float*)d_in[2];
    const float* g1 = (const float*)d_in[3];
    const float* b1 = (const float*)d_in[4];
    const float* W2 = (const float*)d_in[5];
    const float* U2 = (const float*)d_in[6];
    const float* g2 = (const float*)d_in[7];
    const float* b2 = (const float*)d_in[8];
    float* out = (float*)d_out;

    float *w_buf, *hs1, *csum, *csq, *hTs;
    unsigned* cnt;
    cudaGetSymbolAddress((void**)&w_buf, g_w);
    cudaGetSymbolAddress((void**)&hs1,   g_hs1);
    cudaGetSymbolAddress((void**)&csum,  g_colsum);
    cudaGetSymbolAddress((void**)&csq,   g_colsq);
    cudaGetSymbolAddress((void**)&hTs,   g_hTs);
    cudaGetSymbolAddress((void**)&cnt,   g_cnt);

    cudaFuncSetAttribute(rec_kernel, cudaFuncAttributeMaxDynamicSharedMemorySize,
                         REC_SMEM_FLOATS * 4);

    dim3 gproj(16, 250);

    // ---- Layer 1 ----
    sgemm_nt<<<gproj, 256>>>(x, W1, w_buf, F_);
    cudaMemsetAsync(csum, 0, HH_ * 4);
    cudaMemsetAsync(csq,  0, HH_ * 4);
    bn_stats<<<dim3(8, 32), 256>>>(w_buf);
    bn_finalize<<<8, 256>>>(g1, b1);
    cudaMemsetAsync(hTs, 0, 2 * 2 * 1024 * 16 * 4);
    cudaMemsetAsync(cnt, 0, 4 * 4);
    rec_kernel<<<NBLK, 512, REC_SMEM_FLOATS * 4>>>(w_buf, U1, hs1);

    // ---- Layer 2 ----
    sgemm_nt<<<gproj, 256>>>(hs1, W2, w_buf, H_);
    cudaMemsetAsync(csum, 0, HH_ * 4);
    cudaMemsetAsync(csq,  0, HH_ * 4);
    bn_stats<<<dim3(8, 32), 256>>>(w_buf);
    bn_finalize<<<8, 256>>>(g2, b2);
    cudaMemsetAsync(hTs, 0, 2 * 2 * 1024 * 16 * 4);
    cudaMemsetAsync(cnt, 0, 4 * 4);
    rec_kernel<<<NBLK, 512, REC_SMEM_FLOATS * 4>>>(w_buf, U2, out);

    (void)in_sizes; (void)n_in; (void)out_size;
}